// round 5
// baseline (speedup 1.0000x reference)
#include <cuda_runtime.h>
#include <cuda_fp16.h>

#define MAX_EDGES 3200000
#define MAX_NODES 100000
#define EPS 1e-8f

// Scratch (device globals -- no allocation allowed)
__device__ float g_rowsum[MAX_NODES];
__device__ float g_invrowsum[MAX_NODES];
__device__ __align__(16) __half g_emb1h[MAX_NODES * 16];
__device__ __align__(16) __half g_emb2h[MAX_NODES * 16];

// Prep: one thread per embedding ROW (64B in -> 32B out), plus rowsum zeroing.
__global__ void prep_kernel(const float4* __restrict__ emb1,
                            const float4* __restrict__ emb2,
                            int n_nodes) {
    int i = blockIdx.x * blockDim.x + threadIdx.x;
    if (i < 2 * n_nodes) {
        bool first = (i < n_nodes);
        int row = first ? i : i - n_nodes;
        const float4* srcp = (first ? emb1 : emb2) + (size_t)row * 4;
        __half* dstp = (first ? g_emb1h : g_emb2h) + (size_t)row * 16;
        float4 v0 = __ldg(srcp + 0);
        float4 v1 = __ldg(srcp + 1);
        float4 v2 = __ldg(srcp + 2);
        float4 v3 = __ldg(srcp + 3);
        __half2 h0 = __floats2half2_rn(v0.x, v0.y);
        __half2 h1 = __floats2half2_rn(v0.z, v0.w);
        __half2 h2 = __floats2half2_rn(v1.x, v1.y);
        __half2 h3 = __floats2half2_rn(v1.z, v1.w);
        __half2 h4 = __floats2half2_rn(v2.x, v2.y);
        __half2 h5 = __floats2half2_rn(v2.z, v2.w);
        __half2 h6 = __floats2half2_rn(v3.x, v3.y);
        __half2 h7 = __floats2half2_rn(v3.z, v3.w);
        uint4 lo = make_uint4(*(unsigned*)&h0, *(unsigned*)&h1,
                              *(unsigned*)&h2, *(unsigned*)&h3);
        uint4 hi = make_uint4(*(unsigned*)&h4, *(unsigned*)&h5,
                              *(unsigned*)&h6, *(unsigned*)&h7);
        ((uint4*)dstp)[0] = lo;
        ((uint4*)dstp)[1] = hi;
    } else if (i < 3 * n_nodes) {
        g_rowsum[i - 2 * n_nodes] = 0.0f;
    }
}

__device__ __forceinline__ float dot8h(uint4 a, uint4 b) {
    const __half2* ah = (const __half2*)&a;
    const __half2* bh = (const __half2*)&b;
    float acc = 0.0f;
#pragma unroll
    for (int k = 0; k < 4; k++) {
        float2 fa = __half22float2(ah[k]);
        float2 fb = __half22float2(bh[k]);
        acc = fmaf(fa.x, fb.x, acc);
        acc = fmaf(fa.y, fb.y, acc);
    }
    return acc;
}

// Pass 1: 2 lanes per edge-pair-team. Each team handles 2 consecutive edges;
// each lane gathers one 16B half of both rows for BOTH edges (MLP=4),
// shfl-pair reduce, even lane does sigmoid + write-to-out + rowsum RED.
__global__ void edge_score_kernel(const int* __restrict__ src,
                                  const int* __restrict__ dst,
                                  float* __restrict__ out,
                                  int n_edges) {
    int tid = blockIdx.x * blockDim.x + threadIdx.x;
    int team = tid >> 1;
    int half_sel = tid & 1;
    int e0 = team * 2;
    if (e0 >= n_edges) return;
    bool has1 = (e0 + 1 < n_edges);

    int2 s2 = *(const int2*)(src + e0);  // e0 even -> 8B aligned
    int2 d2 = *(const int2*)(dst + e0);

    uint4 av0 = __ldg((const uint4*)(g_emb1h + (size_t)s2.x * 16) + half_sel);
    uint4 bv0 = __ldg((const uint4*)(g_emb2h + (size_t)d2.x * 16) + half_sel);
    uint4 av1, bv1;
    if (has1) {
        av1 = __ldg((const uint4*)(g_emb1h + (size_t)s2.y * 16) + half_sel);
        bv1 = __ldg((const uint4*)(g_emb2h + (size_t)d2.y * 16) + half_sel);
    }

    float acc0 = dot8h(av0, bv0);
    float acc1 = has1 ? dot8h(av1, bv1) : 0.0f;
    acc0 += __shfl_xor_sync(0xffffffffu, acc0, 1);
    acc1 += __shfl_xor_sync(0xffffffffu, acc1, 1);

    if (half_sel == 0) {
        float w0 = __frcp_rn(1.0f + __expf(-acc0));
        out[e0] = w0;
        atomicAdd(&g_rowsum[s2.x], w0);
        if (has1) {
            float w1 = __frcp_rn(1.0f + __expf(-acc1));
            out[e0 + 1] = w1;
            atomicAdd(&g_rowsum[s2.y], w1);
        }
    }
}

// Pass 1.5: reciprocal of row sums
__global__ void inv_rowsum_kernel(int n_nodes) {
    int i = blockIdx.x * blockDim.x + threadIdx.x;
    if (i < n_nodes) g_invrowsum[i] = __frcp_rn(g_rowsum[i] + EPS);
}

// Pass 2: in-place normalize, 4 quads (16 edges) per thread.
// Ownership partition: thread i owns quads {i, i+stride, i+2s, i+3s}, i < stride.
__global__ void normalize_kernel(const int4* __restrict__ src4,
                                 float4* __restrict__ out4,
                                 int n_quads, int stride) {
    int i = blockIdx.x * blockDim.x + threadIdx.x;
    if (i >= stride) return;  // CRITICAL: exact partition, no overlap
    int q[4];
    int4 s[4];
    float4 w[4];
    bool v[4];
#pragma unroll
    for (int k = 0; k < 4; k++) {
        q[k] = i + k * stride;
        v[k] = (q[k] < n_quads);
    }
#pragma unroll
    for (int k = 0; k < 4; k++)
        if (v[k]) s[k] = __ldg(src4 + q[k]);
#pragma unroll
    for (int k = 0; k < 4; k++)
        if (v[k]) w[k] = out4[q[k]];
    float4 inv[4];
#pragma unroll
    for (int k = 0; k < 4; k++) {
        if (v[k]) {
            inv[k].x = __ldg(&g_invrowsum[s[k].x]);
            inv[k].y = __ldg(&g_invrowsum[s[k].y]);
            inv[k].z = __ldg(&g_invrowsum[s[k].z]);
            inv[k].w = __ldg(&g_invrowsum[s[k].w]);
        }
    }
#pragma unroll
    for (int k = 0; k < 4; k++) {
        if (v[k]) {
            float4 o;
            o.x = w[k].x * inv[k].x;
            o.y = w[k].y * inv[k].y;
            o.z = w[k].z * inv[k].z;
            o.w = w[k].w * inv[k].w;
            out4[q[k]] = o;
        }
    }
}

// Tail (n_edges not divisible by 4): in-place on out
__global__ void normalize_tail_kernel(const int* __restrict__ src,
                                      float* __restrict__ out,
                                      int start, int n_edges) {
    int e = start + blockIdx.x * blockDim.x + threadIdx.x;
    if (e >= n_edges) return;
    out[e] = out[e] * __ldg(&g_invrowsum[src[e]]);
}

extern "C" void kernel_launch(void* const* d_in, const int* in_sizes, int n_in,
                              void* d_out, int out_size) {
    const int*    src  = (const int*)d_in[0];
    const int*    dst  = (const int*)d_in[1];
    const float4* emb1 = (const float4*)d_in[2];
    const float4* emb2 = (const float4*)d_in[3];
    float*        out  = (float*)d_out;

    int n_edges = in_sizes[0];
    int n_nodes = in_sizes[2] / 16;

    const int T = 256;

    int prep_items = 3 * n_nodes;
    prep_kernel<<<(prep_items + T - 1) / T, T>>>(emb1, emb2, n_nodes);

    int n_teams = (n_edges + 1) / 2;
    int score_threads = 2 * n_teams;
    edge_score_kernel<<<(score_threads + T - 1) / T, T>>>(src, dst, out, n_edges);

    inv_rowsum_kernel<<<(n_nodes + T - 1) / T, T>>>(n_nodes);

    int n_quads = n_edges / 4;
    if (n_quads > 0) {
        int threads_n = (n_quads + 3) / 4;  // stride = exact owner count
        normalize_kernel<<<(threads_n + T - 1) / T, T>>>((const int4*)src,
                                                         (float4*)out,
                                                         n_quads, threads_n);
    }
    int tail_start = n_quads * 4;
    int tail = n_edges - tail_start;
    if (tail > 0)
        normalize_tail_kernel<<<1, 64>>>(src, out, tail_start, n_edges);
}